// round 2
// baseline (speedup 1.0000x reference)
#include <cuda_runtime.h>
#include <cstdint>

#define N_SRC_MAX 100000
#define N_DST_MAX 50000
#define E_MAX     1250000
#define F         64

// Scratch (device globals; no allocation allowed)
__device__ float  g_neigh[N_DST_MAX * F];   // segment-sum accumulator
__device__ float2 g_huc[N_SRC_MAX];         // {hu, norm_deg_src/q/E}
__device__ float2 g_hvd[N_DST_MAX];         // {hv, norm_deg_dst}

// ---------------------------------------------------------------------------
// Kernel 0: zero the neigh accumulator (float4 stores)
// ---------------------------------------------------------------------------
__global__ void zero_neigh_kernel(int n_dst) {
    int total4 = n_dst * (F / 4);
    int i = blockIdx.x * blockDim.x + threadIdx.x;
    if (i < total4) {
        ((float4*)g_neigh)[i] = make_float4(0.f, 0.f, 0.f, 0.f);
    }
}

// ---------------------------------------------------------------------------
// Kernel 1: per-node projections. One warp per node (src nodes first, then dst).
//   g_huc[i] = { node_feat_src[i,:].sw[:,0],  norm_deg_src[i]/q[i]/E }
//   g_hvd[j] = { node_feat_dst[j,:].sw[:,1],  norm_deg_dst[j] }
// ---------------------------------------------------------------------------
__global__ void node_proj_kernel(const float* __restrict__ nfs,
                                 const float* __restrict__ nfd,
                                 const float* __restrict__ nds,
                                 const float* __restrict__ ndd,
                                 const float* __restrict__ q,
                                 const float* __restrict__ sw,  // [64,2] row-major
                                 int n_src, int n_dst, float inv_e) {
    int warp = (blockIdx.x * blockDim.x + threadIdx.x) >> 5;
    int lane = threadIdx.x & 31;
    if (warp < n_src) {
        int i = warp;
        float v = nfs[i * F + lane]      * sw[lane * 2]
                + nfs[i * F + 32 + lane] * sw[(lane + 32) * 2];
        #pragma unroll
        for (int o = 16; o; o >>= 1) v += __shfl_xor_sync(0xFFFFFFFFu, v, o);
        if (lane == 0) {
            g_huc[i] = make_float2(v, nds[i] / q[i] * inv_e);
        }
    } else if (warp < n_src + n_dst) {
        int i = warp - n_src;
        float v = nfd[i * F + lane]      * sw[lane * 2 + 1]
                + nfd[i * F + 32 + lane] * sw[(lane + 32) * 2 + 1];
        #pragma unroll
        for (int o = 16; o; o >>= 1) v += __shfl_xor_sync(0xFFFFFFFFu, v, o);
        if (lane == 0) g_hvd[i] = make_float2(v, ndd[i]);
    }
}

// ---------------------------------------------------------------------------
// Kernel 2: fused att + scatter.
// Each warp handles 2 edges: lanes [0..15] -> edge e0, lanes [16..31] -> e1.
// Leader lanes (0, 16) load idx + node scalars and compute att; broadcast via
// shfl. Each lane then reds one float4 of hidden[s,:]*att into g_neigh[d,:].
// ---------------------------------------------------------------------------
__global__ void scatter_fused_kernel(const float* __restrict__ hidden,
                                     const int* __restrict__ src_idx,
                                     const int* __restrict__ dst_idx,
                                     int n_edges) {
    int t = blockIdx.x * blockDim.x + threadIdx.x;
    int lane = threadIdx.x & 31;
    int half = lane >> 4;
    int e = (t >> 5) * 2 + half;
    bool valid = (e < n_edges);

    int s = 0, d = 0;
    float att = 0.f;
    if (((lane & 15) == 0) && valid) {
        s = __ldg(&src_idx[e]);
        d = __ldg(&dst_idx[e]);
        float2 uc = g_huc[s];
        float2 vd = g_hvd[d];
        att = uc.y * vd.y * (fmaxf(uc.x + vd.x, 0.f) + 0.1f);
    }
    int src_lane = half << 4;
    s   = __shfl_sync(0xFFFFFFFFu, s,   src_lane);
    d   = __shfl_sync(0xFFFFFFFFu, d,   src_lane);
    att = __shfl_sync(0xFFFFFFFFu, att, src_lane);

    if (valid) {
        int qd = lane & 15;
        float4 h = ((const float4*)hidden)[s * (F / 4) + qd];
        float4 m = make_float4(h.x * att, h.y * att, h.z * att, h.w * att);
        float* p = &g_neigh[d * F + qd * 4];
        asm volatile("red.global.add.v4.f32 [%0], {%1,%2,%3,%4};"
                     :: "l"(p), "f"(m.x), "f"(m.y), "f"(m.z), "f"(m.w)
                     : "memory");
    }
}

// ---------------------------------------------------------------------------
// Kernel 3: FC epilogue. rst = neigh @ fc_weight^T + fc_bias
// ---------------------------------------------------------------------------
#define FC_ROWS 16
__global__ void fc_kernel(const float* __restrict__ fcw,  // [64,64] row-major
                          const float* __restrict__ bias,
                          float* __restrict__ out, int n_dst) {
    __shared__ float fwT[F * F];       // fwT[k*64 + c] = fcw[c*64 + k]
    __shared__ float ns[FC_ROWS * F];
    int tid = threadIdx.x;
    for (int j = tid; j < F * F; j += 256)
        fwT[(j & 63) * F + (j >> 6)] = fcw[j];
    int row0 = blockIdx.x * FC_ROWS;
    for (int j = tid; j < FC_ROWS * F; j += 256) {
        int r = row0 + (j >> 6);
        ns[j] = (r < n_dst) ? g_neigh[r * F + (j & 63)] : 0.f;
    }
    __syncthreads();

    int c  = tid & 63;
    int r0 = tid >> 6;           // 0..3
    float b = bias[c];
    float acc0 = b, acc1 = b, acc2 = b, acc3 = b;
    #pragma unroll
    for (int k = 0; k < F; k++) {
        float w = fwT[k * F + c];
        acc0 += ns[(r0 + 0) * F + k]  * w;
        acc1 += ns[(r0 + 4) * F + k]  * w;
        acc2 += ns[(r0 + 8) * F + k]  * w;
        acc3 += ns[(r0 + 12) * F + k] * w;
    }
    int r;
    r = row0 + r0 + 0;  if (r < n_dst) out[r * F + c] = acc0;
    r = row0 + r0 + 4;  if (r < n_dst) out[r * F + c] = acc1;
    r = row0 + r0 + 8;  if (r < n_dst) out[r * F + c] = acc2;
    r = row0 + r0 + 12; if (r < n_dst) out[r * F + c] = acc3;
}

// ---------------------------------------------------------------------------
// Launch
// ---------------------------------------------------------------------------
extern "C" void kernel_launch(void* const* d_in, const int* in_sizes, int n_in,
                              void* d_out, int out_size) {
    const float* hidden_feat   = (const float*)d_in[0];
    const float* node_feat_src = (const float*)d_in[1];
    const float* node_feat_dst = (const float*)d_in[2];
    const float* norm_deg_src  = (const float*)d_in[3];
    const float* norm_deg_dst  = (const float*)d_in[4];
    const float* q_probs       = (const float*)d_in[5];
    const float* sample_w      = (const float*)d_in[6];
    const float* fc_weight     = (const float*)d_in[7];
    const float* fc_bias       = (const float*)d_in[8];
    const int*   src_idx       = (const int*)d_in[9];
    const int*   dst_idx       = (const int*)d_in[10];

    int n_src   = in_sizes[3];
    int n_dst   = in_sizes[4];
    int n_edges = in_sizes[9];
    if (n_src > N_SRC_MAX) n_src = N_SRC_MAX;
    if (n_dst > N_DST_MAX) n_dst = N_DST_MAX;
    if (n_edges > E_MAX)   n_edges = E_MAX;

    float* out = (float*)d_out;
    float inv_e = 1.0f / (float)n_edges;

    // 0: zero accumulator
    {
        int total4 = n_dst * (F / 4);
        zero_neigh_kernel<<<(total4 + 255) / 256, 256>>>(n_dst);
    }
    // 1: node projections (one warp per node)
    {
        int warps = n_src + n_dst;
        int blocks = (warps * 32 + 255) / 256;
        node_proj_kernel<<<blocks, 256>>>(node_feat_src, node_feat_dst,
                                          norm_deg_src, norm_deg_dst, q_probs,
                                          sample_w, n_src, n_dst, inv_e);
    }
    // 2: fused att + scatter (16 threads / edge, 2 edges / warp)
    {
        int blocks = (n_edges + 15) / 16;   // 16 edges per 256-thread block
        scatter_fused_kernel<<<blocks, 256>>>(hidden_feat, src_idx, dst_idx,
                                              n_edges);
    }
    // 3: FC epilogue
    fc_kernel<<<(n_dst + FC_ROWS - 1) / FC_ROWS, 256>>>(fc_weight, fc_bias,
                                                        out, n_dst);
}

// round 3
// speedup vs baseline: 1.3861x; 1.3861x over previous
#include <cuda_runtime.h>
#include <cstdint>

#define N_SRC_MAX 100000
#define N_DST_MAX 50000
#define E_MAX     1250000
#define F         64

// Scratch (device globals; no allocation allowed)
__device__ float  g_neigh[N_DST_MAX * F];   // segment-sum accumulator
__device__ float2 g_huc[N_SRC_MAX];         // {hu, norm_deg_src/q/E}
__device__ float2 g_hvd[N_DST_MAX];         // {hv, norm_deg_dst}

// ---------------------------------------------------------------------------
// Kernel 0: zero the neigh accumulator (float4 stores)
// ---------------------------------------------------------------------------
__global__ void zero_neigh_kernel(int n_dst) {
    int total4 = n_dst * (F / 4);
    int i = blockIdx.x * blockDim.x + threadIdx.x;
    if (i < total4) {
        ((float4*)g_neigh)[i] = make_float4(0.f, 0.f, 0.f, 0.f);
    }
}

// ---------------------------------------------------------------------------
// Kernel 1: per-node projections. One warp per node (src nodes first, then dst).
// ---------------------------------------------------------------------------
__global__ void node_proj_kernel(const float* __restrict__ nfs,
                                 const float* __restrict__ nfd,
                                 const float* __restrict__ nds,
                                 const float* __restrict__ ndd,
                                 const float* __restrict__ q,
                                 const float* __restrict__ sw,  // [64,2] row-major
                                 int n_src, int n_dst, float inv_e) {
    int warp = (blockIdx.x * blockDim.x + threadIdx.x) >> 5;
    int lane = threadIdx.x & 31;
    if (warp < n_src) {
        int i = warp;
        float v = nfs[i * F + lane]      * sw[lane * 2]
                + nfs[i * F + 32 + lane] * sw[(lane + 32) * 2];
        #pragma unroll
        for (int o = 16; o; o >>= 1) v += __shfl_xor_sync(0xFFFFFFFFu, v, o);
        if (lane == 0) {
            g_huc[i] = make_float2(v, nds[i] / q[i] * inv_e);
        }
    } else if (warp < n_src + n_dst) {
        int i = warp - n_src;
        float v = nfd[i * F + lane]      * sw[lane * 2 + 1]
                + nfd[i * F + 32 + lane] * sw[(lane + 32) * 2 + 1];
        #pragma unroll
        for (int o = 16; o; o >>= 1) v += __shfl_xor_sync(0xFFFFFFFFu, v, o);
        if (lane == 0) g_hvd[i] = make_float2(v, ndd[i]);
    }
}

// ---------------------------------------------------------------------------
// Kernel 2: fused att + scatter, shuffle-free.
// 16 threads per edge; every lane of the 16-group loads the (identical)
// idx / node scalars — same-address broadcast, 1 sector each, L1-resident —
// and computes att redundantly. Each lane then reds one float4 of
// hidden[s,:]*att into g_neigh[d,:].
// ---------------------------------------------------------------------------
__global__ void scatter_fused_kernel(const float* __restrict__ hidden,
                                     const int* __restrict__ src_idx,
                                     const int* __restrict__ dst_idx,
                                     int n_edges) {
    int t = blockIdx.x * blockDim.x + threadIdx.x;
    int e = t >> 4;
    int qd = t & 15;
    if (e < n_edges) {
        int s = __ldg(&src_idx[e]);
        int d = __ldg(&dst_idx[e]);
        float2 uc = g_huc[s];
        float2 vd = g_hvd[d];
        float att = uc.y * vd.y * (fmaxf(uc.x + vd.x, 0.f) + 0.1f);
        float4 h = ((const float4*)hidden)[s * (F / 4) + qd];
        float4 m = make_float4(h.x * att, h.y * att, h.z * att, h.w * att);
        float* p = &g_neigh[d * F + qd * 4];
        asm volatile("red.global.add.v4.f32 [%0], {%1,%2,%3,%4};"
                     :: "l"(p), "f"(m.x), "f"(m.y), "f"(m.z), "f"(m.w)
                     : "memory");
    }
}

// ---------------------------------------------------------------------------
// Kernel 3: FC epilogue. rst = neigh @ fc_weight^T + fc_bias
// 64x64 output tile per block, 256 threads, 4x4 register blocking,
// k-blocked by 4 with float4 LDS on both operands (8 LDS.128 per 64 FMA).
// ---------------------------------------------------------------------------
__global__ void __launch_bounds__(256) fc_kernel(
        const float* __restrict__ fcw,   // [64,64] row-major: fcw[c][k]
        const float* __restrict__ bias,
        float* __restrict__ out, int n_dst) {
    __shared__ float fwT[F * F];          // fwT[k*64 + c] = fcw[c*64 + k]
    __shared__ float ns[F * F];           // ns[r*64 + k]  (64 rows of neigh)
    int tid = threadIdx.x;
    int row0 = blockIdx.x * 64;

    // transpose weights into smem
    #pragma unroll
    for (int j = tid; j < F * F; j += 256)
        fwT[(j & 63) * F + (j >> 6)] = fcw[j];
    // load 64 neigh rows as float4
    #pragma unroll
    for (int j = tid; j < F * F / 4; j += 256) {
        int r = j >> 4;                   // 16 float4 per row
        int o = j & 15;
        int gr = row0 + r;
        float4 v = (gr < n_dst) ? ((const float4*)g_neigh)[gr * 16 + o]
                                : make_float4(0.f, 0.f, 0.f, 0.f);
        ((float4*)ns)[j] = v;
    }
    __syncthreads();

    int tx = tid & 15;          // col group: c0 = tx*4
    int ty = tid >> 4;          // row group: r0 = ty*4
    int c0 = tx * 4;
    int r0 = ty * 4;

    float4 b4 = *(const float4*)&bias[c0];
    float4 acc[4];
    #pragma unroll
    for (int i = 0; i < 4; i++) acc[i] = b4;

    #pragma unroll
    for (int k4 = 0; k4 < F; k4 += 4) {
        float4 a[4], w[4];
        #pragma unroll
        for (int i = 0; i < 4; i++)
            a[i] = *(const float4*)&ns[(r0 + i) * F + k4];
        #pragma unroll
        for (int kk = 0; kk < 4; kk++)
            w[kk] = *(const float4*)&fwT[(k4 + kk) * F + c0];
        #pragma unroll
        for (int i = 0; i < 4; i++) {
            acc[i].x += a[i].x * w[0].x + a[i].y * w[1].x + a[i].z * w[2].x + a[i].w * w[3].x;
            acc[i].y += a[i].x * w[0].y + a[i].y * w[1].y + a[i].z * w[2].y + a[i].w * w[3].y;
            acc[i].z += a[i].x * w[0].z + a[i].y * w[1].z + a[i].z * w[2].z + a[i].w * w[3].z;
            acc[i].w += a[i].x * w[0].w + a[i].y * w[1].w + a[i].z * w[2].w + a[i].w * w[3].w;
        }
    }

    #pragma unroll
    for (int i = 0; i < 4; i++) {
        int r = row0 + r0 + i;
        if (r < n_dst)
            *(float4*)&out[r * F + c0] = acc[i];
    }
}

// ---------------------------------------------------------------------------
// Launch
// ---------------------------------------------------------------------------
extern "C" void kernel_launch(void* const* d_in, const int* in_sizes, int n_in,
                              void* d_out, int out_size) {
    const float* hidden_feat   = (const float*)d_in[0];
    const float* node_feat_src = (const float*)d_in[1];
    const float* node_feat_dst = (const float*)d_in[2];
    const float* norm_deg_src  = (const float*)d_in[3];
    const float* norm_deg_dst  = (const float*)d_in[4];
    const float* q_probs       = (const float*)d_in[5];
    const float* sample_w      = (const float*)d_in[6];
    const float* fc_weight     = (const float*)d_in[7];
    const float* fc_bias       = (const float*)d_in[8];
    const int*   src_idx       = (const int*)d_in[9];
    const int*   dst_idx       = (const int*)d_in[10];

    int n_src   = in_sizes[3];
    int n_dst   = in_sizes[4];
    int n_edges = in_sizes[9];
    if (n_src > N_SRC_MAX) n_src = N_SRC_MAX;
    if (n_dst > N_DST_MAX) n_dst = N_DST_MAX;
    if (n_edges > E_MAX)   n_edges = E_MAX;

    float* out = (float*)d_out;
    float inv_e = 1.0f / (float)n_edges;

    // 0: zero accumulator
    {
        int total4 = n_dst * (F / 4);
        zero_neigh_kernel<<<(total4 + 255) / 256, 256>>>(n_dst);
    }
    // 1: node projections (one warp per node)
    {
        int warps = n_src + n_dst;
        int blocks = (warps * 32 + 255) / 256;
        node_proj_kernel<<<blocks, 256>>>(node_feat_src, node_feat_dst,
                                          norm_deg_src, norm_deg_dst, q_probs,
                                          sample_w, n_src, n_dst, inv_e);
    }
    // 2: fused att + scatter (16 threads / edge, shuffle-free)
    {
        long long total = (long long)n_edges * 16;
        int blocks = (int)((total + 255) / 256);
        scatter_fused_kernel<<<blocks, 256>>>(hidden_feat, src_idx, dst_idx,
                                              n_edges);
    }
    // 3: FC epilogue (64 rows per block)
    fc_kernel<<<(n_dst + 63) / 64, 256>>>(fc_weight, fc_bias, out, n_dst);
}